// round 13
// baseline (speedup 1.0000x reference)
#include <cuda_runtime.h>
#include <cuda_fp16.h>
#include <math.h>
#include <stdint.h>

// Problem constants
#define DIMN  2048
#define BATCH 16384

// Tile constants (verified R10-R12)
#define BK    64
#define ROWB  144u                    // 128B data + 16B pad -> conflict-free LDSM
#define TILEB (128u * ROWB)           // 18432 B per 128x64 fp16 tile
#define NST   3
#define STAGEB (2u * TILEB)           // A + B single tiles = 36864
#define SMEM_GEMM (NST * STAGEB)      // 110592 B -> 2 CTAs/SM

// ---------------------------------------------------------------------------
// Device scratch (static — no runtime allocs)
// ---------------------------------------------------------------------------
__device__ __align__(128) __half g_Dt   [DIMN * DIMN];   // Dt[m][k] = D[k][m]
__device__ __align__(128) __half g_Dm   [DIMN * DIMN];   // Dm[k][n] = D[k][n]
__device__ __align__(128) __half g_W1f  [1024 * DIMN];
__device__ __align__(128) __half g_A1f  [1024 * DIMN];
__device__ __align__(128) __half g_W1ef [1024 * DIMN];
__device__ __align__(128) __half g_x16  [BATCH * DIMN];
__device__ __align__(128) __half g_h1_16[BATCH * 1024];
__device__ __align__(128) __half g_h2_16[BATCH * 512];
__device__ __align__(128) __half g_W2f  [512 * 1024];
__device__ __align__(128) __half g_Wmlf [512 * 512];
__device__ __align__(128) float g_part[2 * 1024 * DIMN]; // split-K=2 partials
__device__ __align__(128) float g_costab[8192];          // cos(pi*q/4096)
__device__ float g_bml[512];
__device__ float g_bscale[DIMN];

// ---------------------------------------------------------------------------
// Band-scale (verified round 1)
// ---------------------------------------------------------------------------
__global__ void build_scale_kernel(const float* __restrict__ fw,
                                   const float* __restrict__ kptr)
{
    int idx = blockIdx.x * blockDim.x + threadIdx.x;
    if (idx >= DIMN) return;
    const float kv = *kptr;
    float val = 1.0f;
    const double step = 2047.0 / 30.0;
    #pragma unroll 1
    for (int i = 0; i < 30; i++) {
        int s = (int)(step * (double)i);
        int e = (i == 29) ? 2047 : (int)(step * (double)(i + 1));
        if (idx >= s && idx < e) {
            float f;
            if (e <= 30) f = 1.0f + fw[i] * kv * (1.0f - (float)i / 30.0f);
            else         f = 1.0f - fw[i] * kv * (1.0f - (float)(i - 30) / 30.0f);
            val = f;
        }
    }
    g_bscale[idx] = val;
}

static __device__ __forceinline__ uint32_t packh(float a, float b)
{
    __half2 t = __floats2half2_rn(a, b);
    return *reinterpret_cast<uint32_t*>(&t);
}

// ---------------------------------------------------------------------------
// cos table: all 8192 distinct values of cos(pi*q/4096) (bit-identical to
// the cospif calls previously made inline)
// ---------------------------------------------------------------------------
__global__ void build_costab_kernel()
{
    int q = blockIdx.x * blockDim.x + threadIdx.x;
    if (q < 8192)
        g_costab[q] = cospif((float)q * (1.0f / 4096.0f));
}

// ---------------------------------------------------------------------------
// Build Dt (D^T) and Dm (D) as fp16 via table gather; 8 elems/thread.
// ---------------------------------------------------------------------------
__global__ void build_D_kernel()
{
    int t = blockIdx.x * blockDim.x + threadIdx.x;   // < DIMN*DIMN/8
    int r  = t >> 8;               // row (2048 cols / 8 = 256 chunks per row)
    int c0 = (t & 255) << 3;       // starting col
    const float n0 = 0.022097086912079612f;  // sqrt(1/2048)
    const float n1 = 0.03125f;               // sqrt(2/2048)
    const float normR = (r == 0) ? n0 : n1;

    uint32_t dt[4], dm[4];
    #pragma unroll
    for (int j = 0; j < 4; j++) {
        int ca = c0 + 2 * j, cb = ca + 1;
        // Dt[r][c] = D[c][r]: q=((2r+1)c)&8191, norm by c
        float ta = g_costab[((2 * r + 1) * ca) & 8191] * ((ca == 0) ? n0 : n1);
        float tb = g_costab[((2 * r + 1) * cb) & 8191] * n1;   // cb>=1 always
        dt[j] = packh(ta, tb);
        // Dm[r][c] = D[r][c]: q=((2c+1)r)&8191, norm by r
        float ma = g_costab[((2 * ca + 1) * r) & 8191] * normR;
        float mb = g_costab[((2 * cb + 1) * r) & 8191] * normR;
        dm[j] = packh(ma, mb);
    }
    size_t off = (size_t)r * DIMN + c0;
    *(uint4*)(g_Dt + off) = *(uint4*)dt;
    *(uint4*)(g_Dm + off) = *(uint4*)dm;
}

// ---------------------------------------------------------------------------
// fp32 -> fp16 convert, 16 elems/thread (n % 16 == 0)
// ---------------------------------------------------------------------------
__global__ void convert_f16(const float* __restrict__ s,
                            __half* __restrict__ d, int n)
{
    int i = (blockIdx.x * blockDim.x + threadIdx.x) << 4;
    if (i >= n) return;
    float4 v0 = *(const float4*)(s + i);
    float4 v1 = *(const float4*)(s + i + 4);
    float4 v2 = *(const float4*)(s + i + 8);
    float4 v3 = *(const float4*)(s + i + 12);
    uint4 b0, b1;
    b0.x = packh(v0.x, v0.y); b0.y = packh(v0.z, v0.w);
    b0.z = packh(v1.x, v1.y); b0.w = packh(v1.z, v1.w);
    b1.x = packh(v2.x, v2.y); b1.y = packh(v2.z, v2.w);
    b1.z = packh(v3.x, v3.y); b1.w = packh(v3.z, v3.w);
    *(uint4*)(d + i)     = b0;
    *(uint4*)(d + i + 8) = b1;
}

// sum 2 split-K fp32 partials -> (optional colscale) -> fp16
// N must be a power of two.
__global__ void reduce2_f16(const float* __restrict__ part,
                            const float* __restrict__ colscale,
                            __half* __restrict__ dst, int n, int N)
{
    int i = (blockIdx.x * blockDim.x + threadIdx.x) << 2;
    if (i >= n) return;
    float4 a = *(const float4*)(part + i);
    float4 b = *(const float4*)(part + (size_t)n + i);
    float v0 = a.x + b.x;
    float v1 = a.y + b.y;
    float v2 = a.z + b.z;
    float v3 = a.w + b.w;
    if (colscale) {
        int col = i & (N - 1);
        v0 *= colscale[col];     v1 *= colscale[col + 1];
        v2 *= colscale[col + 2]; v3 *= colscale[col + 3];
    }
    uint2 buf;
    buf.x = packh(v0, v1);
    buf.y = packh(v2, v3);
    *(uint2*)(dst + i) = buf;
}

__global__ void merge_bias(const float* __restrict__ bmu, const float* __restrict__ blv)
{
    int i = blockIdx.x * blockDim.x + threadIdx.x;
    if (i < 256)      g_bml[i] = bmu[i];
    else if (i < 512) g_bml[i] = blv[i - 256];
}

// ---------------------------------------------------------------------------
// mma.sync / ldmatrix / cp.async helpers
// ---------------------------------------------------------------------------
#define LDSM4(r0, r1, r2, r3, addr)                                            \
    asm volatile("ldmatrix.sync.aligned.m8n8.x4.shared.b16 {%0,%1,%2,%3}, [%4];" \
                 : "=r"(r0), "=r"(r1), "=r"(r2), "=r"(r3) : "r"(addr))

#define MMA_F16(c, a, b)                                                       \
    asm volatile("mma.sync.aligned.m16n8k16.row.col.f32.f16.f16.f32 "          \
                 "{%0,%1,%2,%3},{%4,%5,%6,%7},{%8,%9},{%0,%1,%2,%3};"          \
                 : "+f"((c)[0]), "+f"((c)[1]), "+f"((c)[2]), "+f"((c)[3])      \
                 : "r"((a)[0]), "r"((a)[1]), "r"((a)[2]), "r"((a)[3]),         \
                   "r"((b)[0]), "r"((b)[1]))

#define CP16(sa, ga)                                                           \
    asm volatile("cp.async.cg.shared.global [%0], [%1], 16;"                   \
                 :: "r"(sa), "l"(ga) : "memory")
#define CP_COMMIT() asm volatile("cp.async.commit_group;" ::: "memory")
#define CP_WAIT()   asm volatile("cp.async.wait_group %0;" :: "n"(NST - 2) : "memory")

// ---------------------------------------------------------------------------
// Pure fp16 NT GEMM (verified R11-R12; unchanged).
// C[m][n] = sum_{k in [kbase, kbase+klen)} A[m][k]*B[n][k]; fp32 accumulate.
// 128x128 CTA tile, warp grid 4m x 2n (warp tile 32x64), 3 stages, 2 CTA/SM.
// Output: Cpart (fp32 split-K plane) | Cf (fp32 final mu/logvar) | Cs (fp16).
// ---------------------------------------------------------------------------
__global__ __launch_bounds__(256, 2)
void gemm_f16(const __half* __restrict__ Ap,
              const __half* __restrict__ Bp,
              const float* __restrict__ bias,
              __half* __restrict__ Cs,
              float* __restrict__ Cf,
              float* __restrict__ Cpart,
              int M, int N, int K, int klen, int do_relu)
{
    extern __shared__ __align__(1024) char smem[];
    const uint32_t sb = (uint32_t)__cvta_generic_to_shared(smem);

    const int tid   = threadIdx.x;
    const int lane  = tid & 31;
    const int wid   = tid >> 5;
    const int warpm = wid & 3;
    const int warpn = wid >> 2;
    const int bm = blockIdx.y * 128;
    const int bn = blockIdx.x * 128;
    const int kbase = blockIdx.z * klen;

    const uint32_t aOff = (uint32_t)(warpm * 32 + (lane & 15)) * ROWB
                        + (uint32_t)(lane >> 4) * 16u;
    const uint32_t bOff = (uint32_t)(warpn * 64 + (lane & 7) + ((lane & 16) ? 8 : 0)) * ROWB
                        + (uint32_t)((lane >> 3) & 1) * 16u;

    float acc[2][8][4];
    #pragma unroll
    for (int i = 0; i < 2; i++)
        #pragma unroll
        for (int j = 0; j < 8; j++)
            #pragma unroll
            for (int q = 0; q < 4; q++) acc[i][j][q] = 0.0f;

    const int nk = klen >> 6;

    auto issue_stage = [&](int kt) {
        const uint32_t base = sb + (uint32_t)(kt % NST) * STAGEB;
        const size_t kof = (size_t)kbase + (size_t)kt * BK;
        #pragma unroll
        for (int h = 0; h < 4; h++) {
            const int c   = tid + h * 256;
            const int row = c >> 3;
            const int q   = c & 7;
            const uint32_t so = (uint32_t)row * ROWB + (uint32_t)q * 16u;
            CP16(base + so,         Ap + (size_t)(bm + row) * K + kof + (size_t)q * 8);
            CP16(base + TILEB + so, Bp + (size_t)(bn + row) * K + kof + (size_t)q * 8);
        }
    };

    // F[0..7]=A(mf0,mf1), F[8..23]=B(bf0..bf3)
    auto load_frags = [&](uint32_t base, uint32_t kb, uint32_t* F) {
        const uint32_t bT = base + TILEB;
        #pragma unroll
        for (int mf = 0; mf < 2; mf++) {
            uint32_t ad = base + aOff + (uint32_t)mf * (16u * ROWB) + kb;
            LDSM4(F[mf*4+0], F[mf*4+1], F[mf*4+2], F[mf*4+3], ad);
        }
        #pragma unroll
        for (int bf = 0; bf < 4; bf++) {
            uint32_t bd = bT + bOff + (uint32_t)bf * (16u * ROWB) + kb;
            LDSM4(F[8+bf*4+0], F[8+bf*4+1], F[8+bf*4+2], F[8+bf*4+3], bd);
        }
    };

    auto mma_step = [&](const uint32_t* F) {
        #pragma unroll
        for (int mf = 0; mf < 2; mf++)
            #pragma unroll
            for (int nf = 0; nf < 8; nf++) {
                const uint32_t* BF = &F[8 + (nf >> 1) * 4];
                uint32_t bb[2] = { BF[(nf & 1) ? 2 : 0], BF[(nf & 1) ? 3 : 1] };
                MMA_F16(acc[mf][nf], &F[mf * 4], bb);
            }
    };

    #pragma unroll
    for (int s = 0; s < NST - 1; s++) { issue_stage(s); CP_COMMIT(); }

    uint32_t F[24];

    for (int kt = 0; kt < nk; kt++) {
        CP_WAIT();
        __syncthreads();
        const uint32_t base = sb + (uint32_t)(kt % NST) * STAGEB;
        if (kt + NST - 1 < nk) issue_stage(kt + NST - 1);
        CP_COMMIT();
        #pragma unroll
        for (int ks = 0; ks < 4; ks++) {
            load_frags(base, (uint32_t)ks * 32u, F);
            mma_step(F);
        }
    }

    // ---- epilogue ----
    const int g  = lane >> 2;
    const int tg = lane & 3;
    #pragma unroll
    for (int mf = 0; mf < 2; mf++) {
        const int r0 = bm + warpm * 32 + mf * 16 + g;
        #pragma unroll
        for (int nf = 0; nf < 8; nf++) {
            const int col = bn + warpn * 64 + nf * 8 + tg * 2;
            float v0 = acc[mf][nf][0], v1 = acc[mf][nf][1];
            float v2 = acc[mf][nf][2], v3 = acc[mf][nf][3];

            if (Cpart) {   // split-K fp32 partial, plane = blockIdx.z
                float* base2 = Cpart + (size_t)blockIdx.z * ((size_t)M * N);
                *(float2*)(base2 + (size_t)r0 * N + col)       = make_float2(v0, v1);
                *(float2*)(base2 + (size_t)(r0 + 8) * N + col) = make_float2(v2, v3);
                continue;
            }
            float b0 = bias[col], b1 = bias[col + 1];
            v0 += b0; v1 += b1; v2 += b0; v3 += b1;
            if (do_relu) {
                v0 = fmaxf(v0, 0.0f); v1 = fmaxf(v1, 0.0f);
                v2 = fmaxf(v2, 0.0f); v3 = fmaxf(v3, 0.0f);
            }
            if (Cf) {      // final: N==512; cols [0,256) mu, [256,512) logvar
                float* p0;
                float* p1;
                if (col < 256) {
                    p0 = Cf + (size_t)r0 * 256 + col;
                    p1 = Cf + (size_t)(r0 + 8) * 256 + col;
                } else {
                    float* half2p = Cf + (size_t)BATCH * 256;
                    p0 = half2p + (size_t)r0 * 256 + (col - 256);
                    p1 = half2p + (size_t)(r0 + 8) * 256 + (col - 256);
                }
                *(float2*)p0 = make_float2(v0, v1);
                *(float2*)p1 = make_float2(v2, v3);
            } else {
                *(uint32_t*)(Cs + (size_t)r0 * N + col)       = packh(v0, v1);
                *(uint32_t*)(Cs + (size_t)(r0 + 8) * N + col) = packh(v2, v3);
            }
        }
    }
}

// ---------------------------------------------------------------------------
// Launch: all-fp16 pipeline with table-based D build and split-K=2 weight prep
// ---------------------------------------------------------------------------
extern "C" void kernel_launch(void* const* d_in, const int* in_sizes, int n_in,
                              void* d_out, int out_size)
{
    const float* x   = (const float*)d_in[0];
    const float* fw  = (const float*)d_in[1];
    const float* kp  = (const float*)d_in[2];
    const float* W1  = (const float*)d_in[3];
    const float* b1  = (const float*)d_in[4];
    const float* W2  = (const float*)d_in[5];
    const float* b2  = (const float*)d_in[6];
    const float* Wmu = (const float*)d_in[7];
    const float* bmu = (const float*)d_in[8];
    const float* Wlv = (const float*)d_in[9];
    const float* blv = (const float*)d_in[10];
    float* out = (float*)d_out;

    __half *Dt, *Dm, *W1f, *A1f, *W1ef, *x16, *h1_16, *h2_16, *W2f, *Wmlf;
    float *bml, *bscale, *part;
    cudaGetSymbolAddress((void**)&Dt,    g_Dt);
    cudaGetSymbolAddress((void**)&Dm,    g_Dm);
    cudaGetSymbolAddress((void**)&W1f,   g_W1f);
    cudaGetSymbolAddress((void**)&A1f,   g_A1f);
    cudaGetSymbolAddress((void**)&W1ef,  g_W1ef);
    cudaGetSymbolAddress((void**)&x16,   g_x16);
    cudaGetSymbolAddress((void**)&h1_16, g_h1_16);
    cudaGetSymbolAddress((void**)&h2_16, g_h2_16);
    cudaGetSymbolAddress((void**)&W2f,   g_W2f);
    cudaGetSymbolAddress((void**)&Wmlf,  g_Wmlf);
    cudaGetSymbolAddress((void**)&bml,   g_bml);
    cudaGetSymbolAddress((void**)&bscale, g_bscale);
    cudaGetSymbolAddress((void**)&part,  g_part);

    cudaFuncSetAttribute(gemm_f16,
                         cudaFuncAttributeMaxDynamicSharedMemorySize, SMEM_GEMM);

    build_scale_kernel<<<8, 256>>>(fw, kp);
    build_costab_kernel<<<32, 256>>>();
    build_D_kernel<<<(DIMN * DIMN / 8) / 256, 256>>>();

    convert_f16<<<(BATCH * DIMN / 16 + 255) / 256, 256>>>(x, x16, BATCH * DIMN);
    convert_f16<<<(1024 * DIMN / 16 + 255) / 256, 256>>>(W1, W1f, 1024 * DIMN);
    convert_f16<<<(512 * 1024 / 16 + 255) / 256, 256>>>(W2, W2f, 512 * 1024);
    convert_f16<<<(256 * 512 / 16 + 255) / 256, 256>>>(Wmu, Wmlf, 256 * 512);
    convert_f16<<<(256 * 512 / 16 + 255) / 256, 256>>>(Wlv, Wmlf + 256 * 512, 256 * 512);
    merge_bias<<<2, 256>>>(bmu, blv);

    const int nW = 1024 * DIMN;

    // A1[j][kf] = (sum_n W1[j][n] * D[kf][n]) * bscale[kf]   (split-K=2)
    gemm_f16<<<dim3(16, 8, 2), 256, SMEM_GEMM>>>(
        W1f, Dm, nullptr, nullptr, nullptr, part, 1024, 2048, 2048, 1024, 0);
    reduce2_f16<<<(nW / 4 + 255) / 256, 256>>>(part, bscale, A1f, nW, 2048);

    // W1e[j][m] = sum_kf A1[j][kf] * Dt[m][kf]               (split-K=2)
    gemm_f16<<<dim3(16, 8, 2), 256, SMEM_GEMM>>>(
        A1f, Dt, nullptr, nullptr, nullptr, part, 1024, 2048, 2048, 1024, 0);
    reduce2_f16<<<(nW / 4 + 255) / 256, 256>>>(part, nullptr, W1ef, nW, 2048);

    // h1 = relu(x @ W1e^T + b1)
    gemm_f16<<<dim3(8, 128, 1), 256, SMEM_GEMM>>>(
        x16, W1ef, b1, h1_16, nullptr, nullptr, BATCH, 1024, 2048, 2048, 1);
    // h2 = relu(h1 @ W2^T + b2)
    gemm_f16<<<dim3(4, 128, 1), 256, SMEM_GEMM>>>(
        h1_16, W2f, b2, h2_16, nullptr, nullptr, BATCH, 512, 1024, 1024, 1);
    // [mu | logvar] = h2 @ [Wmu;Wlv]^T + [bmu;blv]
    gemm_f16<<<dim3(4, 128, 1), 256, SMEM_GEMM>>>(
        h2_16, Wmlf, bml, nullptr, out, nullptr, BATCH, 512, 512, 512, 0);
}

// round 14
// speedup vs baseline: 1.0297x; 1.0297x over previous
#include <cuda_runtime.h>
#include <cuda_fp16.h>
#include <math.h>
#include <stdint.h>

// Problem constants
#define DIMN  2048
#define BATCH 16384

// Tile constants (verified R10-R13)
#define BK    64
#define ROWB  144u                    // 128B data + 16B pad -> conflict-free LDSM
#define TILEB (128u * ROWB)           // 18432 B per 128x64 fp16 tile
#define NST   3
#define STAGEB (2u * TILEB)           // A + B single tiles = 36864
#define SMEM_GEMM (NST * STAGEB)      // 110592 B -> 2 CTAs/SM

// ---------------------------------------------------------------------------
// Device scratch (static — no runtime allocs)
// ---------------------------------------------------------------------------
__device__ __align__(128) __half g_Dt   [DIMN * DIMN];   // Dt = Dm^T
__device__ __align__(128) __half g_Dm   [DIMN * DIMN];   // Dm[r][c] = D[r][c]
__device__ __align__(128) __half g_W1f  [1024 * DIMN];
__device__ __align__(128) __half g_A1f  [1024 * DIMN];
__device__ __align__(128) __half g_W1ef [1024 * DIMN];
__device__ __align__(128) __half g_x16  [BATCH * DIMN];
__device__ __align__(128) __half g_h1_16[BATCH * 1024];
__device__ __align__(128) __half g_h2_16[BATCH * 512];
__device__ __align__(128) __half g_W2f  [512 * 1024];
__device__ __align__(128) __half g_Wmlf [512 * 512];
__device__ __align__(128) float g_part[2 * 1024 * DIMN]; // split-K=2 partials
__device__ __align__(128) float g_costab[8192];          // cos(pi*q/4096)
__device__ float g_bml[512];
__device__ float g_bscale[DIMN];

static __device__ __forceinline__ uint32_t packh(float a, float b)
{
    __half2 t = __floats2half2_rn(a, b);
    return *reinterpret_cast<uint32_t*>(&t);
}

// ---------------------------------------------------------------------------
// Fused setup: cos table (8192) + band-scale (2048) + merged bias (512)
// ---------------------------------------------------------------------------
__global__ void setup_kernel(const float* __restrict__ fw,
                             const float* __restrict__ kptr,
                             const float* __restrict__ bmu,
                             const float* __restrict__ blv)
{
    int idx = blockIdx.x * blockDim.x + threadIdx.x;

    if (idx < 8192) {
        g_costab[idx] = cospif((float)idx * (1.0f / 4096.0f));
    } else if (idx < 8192 + DIMN) {
        int i2 = idx - 8192;
        const float kv = *kptr;
        float val = 1.0f;
        const double step = 2047.0 / 30.0;
        #pragma unroll 1
        for (int i = 0; i < 30; i++) {
            int s = (int)(step * (double)i);
            int e = (i == 29) ? 2047 : (int)(step * (double)(i + 1));
            if (i2 >= s && i2 < e) {
                float f;
                if (e <= 30) f = 1.0f + fw[i] * kv * (1.0f - (float)i / 30.0f);
                else         f = 1.0f - fw[i] * kv * (1.0f - (float)(i - 30) / 30.0f);
                val = f;
            }
        }
        g_bscale[i2] = val;
    } else if (idx < 8192 + DIMN + 512) {
        int i3 = idx - 8192 - DIMN;
        g_bml[i3] = (i3 < 256) ? bmu[i3] : blv[i3 - 256];
    }
}

// ---------------------------------------------------------------------------
// Build Dm via Chebyshev recurrence: Dm[r][c] = cos(pi*r*(2c+1)/4096)*s[r].
// Along a row, angle step is constant -> u_{c+1} = 2cos(d)*u_c - u_{c-1}.
// Seeds from exact integer-reduced table (bit-true); 16 elems per thread.
// ---------------------------------------------------------------------------
__global__ void build_Dm_kernel()
{
    int t = blockIdx.x * blockDim.x + threadIdx.x;   // < 2048*128
    int r  = t >> 7;
    int c0 = (t & 127) << 4;
    const float n0 = 0.022097086912079612f;  // sqrt(1/2048)
    const float n1 = 0.03125f;               // sqrt(2/2048)
    const float normR = (r == 0) ? n0 : n1;

    float u0 = g_costab[((2 * c0 + 1) * r) & 8191];
    float u1 = g_costab[((2 * c0 + 3) * r) & 8191];
    const float K2 = 2.0f * g_costab[(2 * r) & 8191];

    uint32_t buf[8];
    float prev = u0, cur = u1;
    #pragma unroll
    for (int j = 0; j < 8; j++) {
        float a = prev, b = cur;
        buf[j] = packh(a * normR, b * normR);
        float nxt1 = fmaf(K2, b, -a);        // u_{c+2}
        float nxt2 = fmaf(K2, nxt1, -b);     // u_{c+3}
        prev = nxt1; cur = nxt2;
    }
    *(uint4*)(g_Dm + (size_t)r * DIMN + c0)     = *(uint4*)&buf[0];
    *(uint4*)(g_Dm + (size_t)r * DIMN + c0 + 8) = *(uint4*)&buf[4];
}

// ---------------------------------------------------------------------------
// Dt = Dm^T  (tiled smem transpose, 64x64 fp16 tiles)
// ---------------------------------------------------------------------------
__global__ void transpose_D_kernel()
{
    __shared__ __half tile[64][72];   // 72 pad -> reduced bank conflicts
    const int tid = threadIdx.x;
    const int lr = tid >> 2;          // 0..63
    const int lc = (tid & 3) << 4;    // 0,16,32,48

    // load 64x64 tile from Dm at (by*64, bx*64)
    const __half* src = g_Dm + (size_t)(blockIdx.y * 64 + lr) * DIMN
                             + blockIdx.x * 64 + lc;
    *(uint4*)&tile[lr][lc]     = *(const uint4*)src;
    *(uint4*)&tile[lr][lc + 8] = *(const uint4*)(src + 8);
    __syncthreads();

    // write transposed: Dt[bx*64+lr][by*64+lc+j] = tile[lc+j][lr]
    __half out[16];
    #pragma unroll
    for (int j = 0; j < 16; j++) out[j] = tile[lc + j][lr];
    __half* dst = g_Dt + (size_t)(blockIdx.x * 64 + lr) * DIMN
                       + blockIdx.y * 64 + lc;
    *(uint4*)dst       = *(uint4*)&out[0];
    *(uint4*)(dst + 8) = *(uint4*)&out[8];
}

// ---------------------------------------------------------------------------
// fp32 -> fp16 convert, 16 elems/thread (verified R13: 74% HBM)
// ---------------------------------------------------------------------------
__global__ void convert_f16(const float* __restrict__ s,
                            __half* __restrict__ d, int n)
{
    int i = (blockIdx.x * blockDim.x + threadIdx.x) << 4;
    if (i >= n) return;
    float4 v0 = *(const float4*)(s + i);
    float4 v1 = *(const float4*)(s + i + 4);
    float4 v2 = *(const float4*)(s + i + 8);
    float4 v3 = *(const float4*)(s + i + 12);
    uint4 b0, b1;
    b0.x = packh(v0.x, v0.y); b0.y = packh(v0.z, v0.w);
    b0.z = packh(v1.x, v1.y); b0.w = packh(v1.z, v1.w);
    b1.x = packh(v2.x, v2.y); b1.y = packh(v2.z, v2.w);
    b1.z = packh(v3.x, v3.y); b1.w = packh(v3.z, v3.w);
    *(uint4*)(d + i)     = b0;
    *(uint4*)(d + i + 8) = b1;
}

// sum 2 split-K fp32 partials -> (optional colscale) -> fp16
__global__ void reduce2_f16(const float* __restrict__ part,
                            const float* __restrict__ colscale,
                            __half* __restrict__ dst, int n, int N)
{
    int i = (blockIdx.x * blockDim.x + threadIdx.x) << 2;
    if (i >= n) return;
    float4 a = *(const float4*)(part + i);
    float4 b = *(const float4*)(part + (size_t)n + i);
    float v0 = a.x + b.x;
    float v1 = a.y + b.y;
    float v2 = a.z + b.z;
    float v3 = a.w + b.w;
    if (colscale) {
        int col = i & (N - 1);
        v0 *= colscale[col];     v1 *= colscale[col + 1];
        v2 *= colscale[col + 2]; v3 *= colscale[col + 3];
    }
    uint2 buf;
    buf.x = packh(v0, v1);
    buf.y = packh(v2, v3);
    *(uint2*)(dst + i) = buf;
}

// ---------------------------------------------------------------------------
// mma.sync / ldmatrix / cp.async helpers
// ---------------------------------------------------------------------------
#define LDSM4(r0, r1, r2, r3, addr)                                            \
    asm volatile("ldmatrix.sync.aligned.m8n8.x4.shared.b16 {%0,%1,%2,%3}, [%4];" \
                 : "=r"(r0), "=r"(r1), "=r"(r2), "=r"(r3) : "r"(addr))

#define MMA_F16(c, a, b)                                                       \
    asm volatile("mma.sync.aligned.m16n8k16.row.col.f32.f16.f16.f32 "          \
                 "{%0,%1,%2,%3},{%4,%5,%6,%7},{%8,%9},{%0,%1,%2,%3};"          \
                 : "+f"((c)[0]), "+f"((c)[1]), "+f"((c)[2]), "+f"((c)[3])      \
                 : "r"((a)[0]), "r"((a)[1]), "r"((a)[2]), "r"((a)[3]),         \
                   "r"((b)[0]), "r"((b)[1]))

#define CP16(sa, ga)                                                           \
    asm volatile("cp.async.cg.shared.global [%0], [%1], 16;"                   \
                 :: "r"(sa), "l"(ga) : "memory")
#define CP_COMMIT() asm volatile("cp.async.commit_group;" ::: "memory")
#define CP_WAIT()   asm volatile("cp.async.wait_group %0;" :: "n"(NST - 2) : "memory")

// ---------------------------------------------------------------------------
// Pure fp16 NT GEMM (verified R11-R13; unchanged).
// ---------------------------------------------------------------------------
__global__ __launch_bounds__(256, 2)
void gemm_f16(const __half* __restrict__ Ap,
              const __half* __restrict__ Bp,
              const float* __restrict__ bias,
              __half* __restrict__ Cs,
              float* __restrict__ Cf,
              float* __restrict__ Cpart,
              int M, int N, int K, int klen, int do_relu)
{
    extern __shared__ __align__(1024) char smem[];
    const uint32_t sb = (uint32_t)__cvta_generic_to_shared(smem);

    const int tid   = threadIdx.x;
    const int lane  = tid & 31;
    const int wid   = tid >> 5;
    const int warpm = wid & 3;
    const int warpn = wid >> 2;
    const int bm = blockIdx.y * 128;
    const int bn = blockIdx.x * 128;
    const int kbase = blockIdx.z * klen;

    const uint32_t aOff = (uint32_t)(warpm * 32 + (lane & 15)) * ROWB
                        + (uint32_t)(lane >> 4) * 16u;
    const uint32_t bOff = (uint32_t)(warpn * 64 + (lane & 7) + ((lane & 16) ? 8 : 0)) * ROWB
                        + (uint32_t)((lane >> 3) & 1) * 16u;

    float acc[2][8][4];
    #pragma unroll
    for (int i = 0; i < 2; i++)
        #pragma unroll
        for (int j = 0; j < 8; j++)
            #pragma unroll
            for (int q = 0; q < 4; q++) acc[i][j][q] = 0.0f;

    const int nk = klen >> 6;

    auto issue_stage = [&](int kt) {
        const uint32_t base = sb + (uint32_t)(kt % NST) * STAGEB;
        const size_t kof = (size_t)kbase + (size_t)kt * BK;
        #pragma unroll
        for (int h = 0; h < 4; h++) {
            const int c   = tid + h * 256;
            const int row = c >> 3;
            const int q   = c & 7;
            const uint32_t so = (uint32_t)row * ROWB + (uint32_t)q * 16u;
            CP16(base + so,         Ap + (size_t)(bm + row) * K + kof + (size_t)q * 8);
            CP16(base + TILEB + so, Bp + (size_t)(bn + row) * K + kof + (size_t)q * 8);
        }
    };

    auto load_frags = [&](uint32_t base, uint32_t kb, uint32_t* F) {
        const uint32_t bT = base + TILEB;
        #pragma unroll
        for (int mf = 0; mf < 2; mf++) {
            uint32_t ad = base + aOff + (uint32_t)mf * (16u * ROWB) + kb;
            LDSM4(F[mf*4+0], F[mf*4+1], F[mf*4+2], F[mf*4+3], ad);
        }
        #pragma unroll
        for (int bf = 0; bf < 4; bf++) {
            uint32_t bd = bT + bOff + (uint32_t)bf * (16u * ROWB) + kb;
            LDSM4(F[8+bf*4+0], F[8+bf*4+1], F[8+bf*4+2], F[8+bf*4+3], bd);
        }
    };

    auto mma_step = [&](const uint32_t* F) {
        #pragma unroll
        for (int mf = 0; mf < 2; mf++)
            #pragma unroll
            for (int nf = 0; nf < 8; nf++) {
                const uint32_t* BF = &F[8 + (nf >> 1) * 4];
                uint32_t bb[2] = { BF[(nf & 1) ? 2 : 0], BF[(nf & 1) ? 3 : 1] };
                MMA_F16(acc[mf][nf], &F[mf * 4], bb);
            }
    };

    #pragma unroll
    for (int s = 0; s < NST - 1; s++) { issue_stage(s); CP_COMMIT(); }

    uint32_t F[24];

    for (int kt = 0; kt < nk; kt++) {
        CP_WAIT();
        __syncthreads();
        const uint32_t base = sb + (uint32_t)(kt % NST) * STAGEB;
        if (kt + NST - 1 < nk) issue_stage(kt + NST - 1);
        CP_COMMIT();
        #pragma unroll
        for (int ks = 0; ks < 4; ks++) {
            load_frags(base, (uint32_t)ks * 32u, F);
            mma_step(F);
        }
    }

    // ---- epilogue ----
    const int g  = lane >> 2;
    const int tg = lane & 3;
    #pragma unroll
    for (int mf = 0; mf < 2; mf++) {
        const int r0 = bm + warpm * 32 + mf * 16 + g;
        #pragma unroll
        for (int nf = 0; nf < 8; nf++) {
            const int col = bn + warpn * 64 + nf * 8 + tg * 2;
            float v0 = acc[mf][nf][0], v1 = acc[mf][nf][1];
            float v2 = acc[mf][nf][2], v3 = acc[mf][nf][3];

            if (Cpart) {   // split-K fp32 partial, plane = blockIdx.z
                float* base2 = Cpart + (size_t)blockIdx.z * ((size_t)M * N);
                *(float2*)(base2 + (size_t)r0 * N + col)       = make_float2(v0, v1);
                *(float2*)(base2 + (size_t)(r0 + 8) * N + col) = make_float2(v2, v3);
                continue;
            }
            float b0 = bias[col], b1 = bias[col + 1];
            v0 += b0; v1 += b1; v2 += b0; v3 += b1;
            if (do_relu) {
                v0 = fmaxf(v0, 0.0f); v1 = fmaxf(v1, 0.0f);
                v2 = fmaxf(v2, 0.0f); v3 = fmaxf(v3, 0.0f);
            }
            if (Cf) {      // final: N==512; cols [0,256) mu, [256,512) logvar
                float* p0;
                float* p1;
                if (col < 256) {
                    p0 = Cf + (size_t)r0 * 256 + col;
                    p1 = Cf + (size_t)(r0 + 8) * 256 + col;
                } else {
                    float* half2p = Cf + (size_t)BATCH * 256;
                    p0 = half2p + (size_t)r0 * 256 + (col - 256);
                    p1 = half2p + (size_t)(r0 + 8) * 256 + (col - 256);
                }
                *(float2*)p0 = make_float2(v0, v1);
                *(float2*)p1 = make_float2(v2, v3);
            } else {
                *(uint32_t*)(Cs + (size_t)r0 * N + col)       = packh(v0, v1);
                *(uint32_t*)(Cs + (size_t)(r0 + 8) * N + col) = packh(v2, v3);
            }
        }
    }
}

// ---------------------------------------------------------------------------
// Launch
// ---------------------------------------------------------------------------
extern "C" void kernel_launch(void* const* d_in, const int* in_sizes, int n_in,
                              void* d_out, int out_size)
{
    const float* x   = (const float*)d_in[0];
    const float* fw  = (const float*)d_in[1];
    const float* kp  = (const float*)d_in[2];
    const float* W1  = (const float*)d_in[3];
    const float* b1  = (const float*)d_in[4];
    const float* W2  = (const float*)d_in[5];
    const float* b2  = (const float*)d_in[6];
    const float* Wmu = (const float*)d_in[7];
    const float* bmu = (const float*)d_in[8];
    const float* Wlv = (const float*)d_in[9];
    const float* blv = (const float*)d_in[10];
    float* out = (float*)d_out;

    __half *Dt, *Dm, *W1f, *A1f, *W1ef, *x16, *h1_16, *h2_16, *W2f, *Wmlf;
    float *bml, *bscale, *part;
    cudaGetSymbolAddress((void**)&Dt,    g_Dt);
    cudaGetSymbolAddress((void**)&Dm,    g_Dm);
    cudaGetSymbolAddress((void**)&W1f,   g_W1f);
    cudaGetSymbolAddress((void**)&A1f,   g_A1f);
    cudaGetSymbolAddress((void**)&W1ef,  g_W1ef);
    cudaGetSymbolAddress((void**)&x16,   g_x16);
    cudaGetSymbolAddress((void**)&h1_16, g_h1_16);
    cudaGetSymbolAddress((void**)&h2_16, g_h2_16);
    cudaGetSymbolAddress((void**)&W2f,   g_W2f);
    cudaGetSymbolAddress((void**)&Wmlf,  g_Wmlf);
    cudaGetSymbolAddress((void**)&bml,   g_bml);
    cudaGetSymbolAddress((void**)&bscale, g_bscale);
    cudaGetSymbolAddress((void**)&part,  g_part);

    cudaFuncSetAttribute(gemm_f16,
                         cudaFuncAttributeMaxDynamicSharedMemorySize, SMEM_GEMM);

    // setup: costab + bscale + bml in one launch (8192+2048+512 = 10752)
    setup_kernel<<<42, 256>>>(fw, kp, bmu, blv);
    // Dm via Chebyshev recurrence, Dt via transpose
    build_Dm_kernel<<<(DIMN * 128) / 256, 256>>>();
    transpose_D_kernel<<<dim3(32, 32), 256>>>();

    convert_f16<<<(BATCH * DIMN / 16 + 255) / 256, 256>>>(x, x16, BATCH * DIMN);
    convert_f16<<<(1024 * DIMN / 16 + 255) / 256, 256>>>(W1, W1f, 1024 * DIMN);
    convert_f16<<<(512 * 1024 / 16 + 255) / 256, 256>>>(W2, W2f, 512 * 1024);
    convert_f16<<<(256 * 512 / 16 + 255) / 256, 256>>>(Wmu, Wmlf, 256 * 512);
    convert_f16<<<(256 * 512 / 16 + 255) / 256, 256>>>(Wlv, Wmlf + 256 * 512, 256 * 512);

    const int nW = 1024 * DIMN;

    // A1[j][kf] = (sum_n W1[j][n] * Dm[kf][n]) * bscale[kf]  (split-K=2)
    gemm_f16<<<dim3(16, 8, 2), 256, SMEM_GEMM>>>(
        W1f, Dm, nullptr, nullptr, nullptr, part, 1024, 2048, 2048, 1024, 0);
    reduce2_f16<<<(nW / 4 + 255) / 256, 256>>>(part, bscale, A1f, nW, 2048);

    // W1e[j][m] = sum_kf A1[j][kf] * Dt[m][kf]               (split-K=2)
    gemm_f16<<<dim3(16, 8, 2), 256, SMEM_GEMM>>>(
        A1f, Dt, nullptr, nullptr, nullptr, part, 1024, 2048, 2048, 1024, 0);
    reduce2_f16<<<(nW / 4 + 255) / 256, 256>>>(part, nullptr, W1ef, nW, 2048);

    // h1 = relu(x @ W1e^T + b1)
    gemm_f16<<<dim3(8, 128, 1), 256, SMEM_GEMM>>>(
        x16, W1ef, b1, h1_16, nullptr, nullptr, BATCH, 1024, 2048, 2048, 1);
    // h2 = relu(h1 @ W2^T + b2)
    gemm_f16<<<dim3(4, 128, 1), 256, SMEM_GEMM>>>(
        h1_16, W2f, b2, h2_16, nullptr, nullptr, BATCH, 512, 1024, 1024, 1);
    // [mu | logvar] = h2 @ [Wmu;Wlv]^T + [bmu;blv]
    gemm_f16<<<dim3(4, 128, 1), 256, SMEM_GEMM>>>(
        h2_16, Wmlf, bml, nullptr, out, nullptr, BATCH, 512, 512, 512, 0);
}

// round 15
// speedup vs baseline: 1.0612x; 1.0306x over previous
#include <cuda_runtime.h>
#include <cuda_fp16.h>
#include <math.h>
#include <stdint.h>

// Problem constants
#define DIMN  2048
#define BATCH 16384

// Tile constants (verified R10-R14)
#define BK    64
#define ROWB  144u                    // 128B data + 16B pad -> conflict-free LDSM
#define TILEB (128u * ROWB)           // 18432 B per 128x64 fp16 tile
#define NST   3
#define STAGEB (2u * TILEB)           // A + B single tiles = 36864
#define SMEM_GEMM (NST * STAGEB)      // 110592 B -> 2 CTAs/SM

// Convert sizes
#define NX (BATCH * DIMN)             // 33554432
#define N1 (1024 * DIMN)              // 2097152
#define N2 (512 * 1024)               // 524288
#define N3 (256 * 512)                // 131072
#define NTOT (NX + N1 + N2 + 2 * N3)

// ---------------------------------------------------------------------------
// Device scratch (static — no runtime allocs)
// ---------------------------------------------------------------------------
__device__ __align__(128) __half g_Dt   [DIMN * DIMN];   // Dt[m][kf]=D[kf][m]
__device__ __align__(128) __half g_Dm   [DIMN * DIMN];   // Dm[r][c] = D[r][c]
__device__ __align__(128) __half g_W1f  [1024 * DIMN];
__device__ __align__(128) __half g_A1f  [1024 * DIMN];
__device__ __align__(128) __half g_W1ef [1024 * DIMN];
__device__ __align__(128) __half g_x16  [BATCH * DIMN];
__device__ __align__(128) __half g_h1_16[BATCH * 1024];
__device__ __align__(128) __half g_h2_16[BATCH * 512];
__device__ __align__(128) __half g_W2f  [512 * 1024];
__device__ __align__(128) __half g_Wmlf [512 * 512];
__device__ __align__(128) float g_part[2 * 1024 * DIMN]; // split-K=2 partials
__device__ __align__(128) float g_costab[8192];          // cos(pi*q/4096)
__device__ float g_bml[512];
__device__ float g_bscale[DIMN];

static __device__ __forceinline__ uint32_t packh(float a, float b)
{
    __half2 t = __floats2half2_rn(a, b);
    return *reinterpret_cast<uint32_t*>(&t);
}

// ---------------------------------------------------------------------------
// Fused setup: cos table (8192) + band-scale (2048) + merged bias (512)
// ---------------------------------------------------------------------------
__global__ void setup_kernel(const float* __restrict__ fw,
                             const float* __restrict__ kptr,
                             const float* __restrict__ bmu,
                             const float* __restrict__ blv)
{
    int idx = blockIdx.x * blockDim.x + threadIdx.x;

    if (idx < 8192) {
        g_costab[idx] = cospif((float)idx * (1.0f / 4096.0f));
    } else if (idx < 8192 + DIMN) {
        int i2 = idx - 8192;
        const float kv = *kptr;
        float val = 1.0f;
        const double step = 2047.0 / 30.0;
        #pragma unroll 1
        for (int i = 0; i < 30; i++) {
            int s = (int)(step * (double)i);
            int e = (i == 29) ? 2047 : (int)(step * (double)(i + 1));
            if (i2 >= s && i2 < e) {
                float f;
                if (e <= 30) f = 1.0f + fw[i] * kv * (1.0f - (float)i / 30.0f);
                else         f = 1.0f - fw[i] * kv * (1.0f - (float)(i - 30) / 30.0f);
                val = f;
            }
        }
        g_bscale[i2] = val;
    } else if (idx < 8192 + DIMN + 512) {
        int i3 = idx - 8192 - DIMN;
        g_bml[i3] = (i3 < 256) ? bmu[i3] : blv[i3 - 256];
    }
}

// ---------------------------------------------------------------------------
// Build BOTH Dm and Dt via per-row Chebyshev recurrences (no transpose).
//  Dm[r][c]  = cos(pi*r*(2c+1)/4096) * s(r)   step angle d = 2r*pi/4096
//  Dt[r][kf] = cos(pi*kf*(2r+1)/4096) * s(kf) step angle d = (2r+1)*pi/4096
// Seeds from exact integer-reduced table; 32 elems per thread per matrix.
// ---------------------------------------------------------------------------
__global__ void build_D_kernel()
{
    int t = blockIdx.x * blockDim.x + threadIdx.x;   // < 2048*64
    int r  = t >> 6;
    int c0 = (t & 63) << 5;
    const float n0 = 0.022097086912079612f;  // sqrt(1/2048)
    const float n1 = 0.03125f;               // sqrt(2/2048)
    const float normR = (r == 0) ? n0 : n1;

    // Dm recurrence state
    float pm = g_costab[((2 * c0 + 1) * r) & 8191];
    float cm = g_costab[((2 * c0 + 3) * r) & 8191];
    const float Km = 2.0f * g_costab[(2 * r) & 8191];
    // Dt recurrence state
    float pt = g_costab[((2 * r + 1) * c0) & 8191];
    float ct = g_costab[((2 * r + 1) * (c0 + 1)) & 8191];
    const float Kt = 2.0f * g_costab[(2 * r + 1) & 8191];

    size_t rowoff = (size_t)r * DIMN;
    #pragma unroll
    for (int chunk = 0; chunk < 4; chunk++) {
        uint32_t bm_[4], bt_[4];
        #pragma unroll
        for (int j = 0; j < 4; j++) {
            int c = c0 + chunk * 8 + 2 * j;
            // Dm: norm by row
            bm_[j] = packh(pm * normR, cm * normR);
            float m2 = fmaf(Km, cm, -pm);
            float m3 = fmaf(Km, m2, -cm);
            pm = m2; cm = m3;
            // Dt: norm by column
            float na = (c == 0) ? n0 : n1;
            bt_[j] = packh(pt * na, ct * n1);
            float t2 = fmaf(Kt, ct, -pt);
            float t3 = fmaf(Kt, t2, -ct);
            pt = t2; ct = t3;
        }
        *(uint4*)(g_Dm + rowoff + c0 + chunk * 8) = *(uint4*)bm_;
        *(uint4*)(g_Dt + rowoff + c0 + chunk * 8) = *(uint4*)bt_;
    }
}

// ---------------------------------------------------------------------------
// Fused fp32 -> fp16 convert for x, W1, W2, Wmu, Wlv (16 elems/thread).
// All section sizes are multiples of 16; ranges map by linear index.
// ---------------------------------------------------------------------------
static __device__ __forceinline__ void cvt16(const float* __restrict__ s,
                                             __half* __restrict__ d, int i)
{
    float4 v0 = *(const float4*)(s + i);
    float4 v1 = *(const float4*)(s + i + 4);
    float4 v2 = *(const float4*)(s + i + 8);
    float4 v3 = *(const float4*)(s + i + 12);
    uint4 b0, b1;
    b0.x = packh(v0.x, v0.y); b0.y = packh(v0.z, v0.w);
    b0.z = packh(v1.x, v1.y); b0.w = packh(v1.z, v1.w);
    b1.x = packh(v2.x, v2.y); b1.y = packh(v2.z, v2.w);
    b1.z = packh(v3.x, v3.y); b1.w = packh(v3.z, v3.w);
    *(uint4*)(d + i)     = b0;
    *(uint4*)(d + i + 8) = b1;
}

__global__ void convert_all(const float* __restrict__ x,
                            const float* __restrict__ W1,
                            const float* __restrict__ W2,
                            const float* __restrict__ Wmu,
                            const float* __restrict__ Wlv)
{
    int i = (blockIdx.x * blockDim.x + threadIdx.x) << 4;
    if (i < NX) {
        cvt16(x, g_x16, i);
    } else if (i < NX + N1) {
        cvt16(W1, g_W1f, i - NX);
    } else if (i < NX + N1 + N2) {
        cvt16(W2, g_W2f, i - NX - N1);
    } else if (i < NX + N1 + N2 + N3) {
        cvt16(Wmu, g_Wmlf, i - NX - N1 - N2);
    } else if (i < NTOT) {
        cvt16(Wlv, g_Wmlf + N3, i - NX - N1 - N2 - N3);
    }
}

// sum 2 split-K fp32 partials -> (optional colscale) -> fp16
__global__ void reduce2_f16(const float* __restrict__ part,
                            const float* __restrict__ colscale,
                            __half* __restrict__ dst, int n, int N)
{
    int i = (blockIdx.x * blockDim.x + threadIdx.x) << 2;
    if (i >= n) return;
    float4 a = *(const float4*)(part + i);
    float4 b = *(const float4*)(part + (size_t)n + i);
    float v0 = a.x + b.x;
    float v1 = a.y + b.y;
    float v2 = a.z + b.z;
    float v3 = a.w + b.w;
    if (colscale) {
        int col = i & (N - 1);
        v0 *= colscale[col];     v1 *= colscale[col + 1];
        v2 *= colscale[col + 2]; v3 *= colscale[col + 3];
    }
    uint2 buf;
    buf.x = packh(v0, v1);
    buf.y = packh(v2, v3);
    *(uint2*)(dst + i) = buf;
}

// ---------------------------------------------------------------------------
// mma.sync / ldmatrix / cp.async helpers
// ---------------------------------------------------------------------------
#define LDSM4(r0, r1, r2, r3, addr)                                            \
    asm volatile("ldmatrix.sync.aligned.m8n8.x4.shared.b16 {%0,%1,%2,%3}, [%4];" \
                 : "=r"(r0), "=r"(r1), "=r"(r2), "=r"(r3) : "r"(addr))

#define MMA_F16(c, a, b)                                                       \
    asm volatile("mma.sync.aligned.m16n8k16.row.col.f32.f16.f16.f32 "          \
                 "{%0,%1,%2,%3},{%4,%5,%6,%7},{%8,%9},{%0,%1,%2,%3};"          \
                 : "+f"((c)[0]), "+f"((c)[1]), "+f"((c)[2]), "+f"((c)[3])      \
                 : "r"((a)[0]), "r"((a)[1]), "r"((a)[2]), "r"((a)[3]),         \
                   "r"((b)[0]), "r"((b)[1]))

#define CP16(sa, ga)                                                           \
    asm volatile("cp.async.cg.shared.global [%0], [%1], 16;"                   \
                 :: "r"(sa), "l"(ga) : "memory")
#define CP_COMMIT() asm volatile("cp.async.commit_group;" ::: "memory")
#define CP_WAIT()   asm volatile("cp.async.wait_group %0;" :: "n"(NST - 2) : "memory")

// ---------------------------------------------------------------------------
// Pure fp16 NT GEMM (verified R11-R14; unchanged).
// ---------------------------------------------------------------------------
__global__ __launch_bounds__(256, 2)
void gemm_f16(const __half* __restrict__ Ap,
              const __half* __restrict__ Bp,
              const float* __restrict__ bias,
              __half* __restrict__ Cs,
              float* __restrict__ Cf,
              float* __restrict__ Cpart,
              int M, int N, int K, int klen, int do_relu)
{
    extern __shared__ __align__(1024) char smem[];
    const uint32_t sb = (uint32_t)__cvta_generic_to_shared(smem);

    const int tid   = threadIdx.x;
    const int lane  = tid & 31;
    const int wid   = tid >> 5;
    const int warpm = wid & 3;
    const int warpn = wid >> 2;
    const int bm = blockIdx.y * 128;
    const int bn = blockIdx.x * 128;
    const int kbase = blockIdx.z * klen;

    const uint32_t aOff = (uint32_t)(warpm * 32 + (lane & 15)) * ROWB
                        + (uint32_t)(lane >> 4) * 16u;
    const uint32_t bOff = (uint32_t)(warpn * 64 + (lane & 7) + ((lane & 16) ? 8 : 0)) * ROWB
                        + (uint32_t)((lane >> 3) & 1) * 16u;

    float acc[2][8][4];
    #pragma unroll
    for (int i = 0; i < 2; i++)
        #pragma unroll
        for (int j = 0; j < 8; j++)
            #pragma unroll
            for (int q = 0; q < 4; q++) acc[i][j][q] = 0.0f;

    const int nk = klen >> 6;

    auto issue_stage = [&](int kt) {
        const uint32_t base = sb + (uint32_t)(kt % NST) * STAGEB;
        const size_t kof = (size_t)kbase + (size_t)kt * BK;
        #pragma unroll
        for (int h = 0; h < 4; h++) {
            const int c   = tid + h * 256;
            const int row = c >> 3;
            const int q   = c & 7;
            const uint32_t so = (uint32_t)row * ROWB + (uint32_t)q * 16u;
            CP16(base + so,         Ap + (size_t)(bm + row) * K + kof + (size_t)q * 8);
            CP16(base + TILEB + so, Bp + (size_t)(bn + row) * K + kof + (size_t)q * 8);
        }
    };

    auto load_frags = [&](uint32_t base, uint32_t kb, uint32_t* F) {
        const uint32_t bT = base + TILEB;
        #pragma unroll
        for (int mf = 0; mf < 2; mf++) {
            uint32_t ad = base + aOff + (uint32_t)mf * (16u * ROWB) + kb;
            LDSM4(F[mf*4+0], F[mf*4+1], F[mf*4+2], F[mf*4+3], ad);
        }
        #pragma unroll
        for (int bf = 0; bf < 4; bf++) {
            uint32_t bd = bT + bOff + (uint32_t)bf * (16u * ROWB) + kb;
            LDSM4(F[8+bf*4+0], F[8+bf*4+1], F[8+bf*4+2], F[8+bf*4+3], bd);
        }
    };

    auto mma_step = [&](const uint32_t* F) {
        #pragma unroll
        for (int mf = 0; mf < 2; mf++)
            #pragma unroll
            for (int nf = 0; nf < 8; nf++) {
                const uint32_t* BF = &F[8 + (nf >> 1) * 4];
                uint32_t bb[2] = { BF[(nf & 1) ? 2 : 0], BF[(nf & 1) ? 3 : 1] };
                MMA_F16(acc[mf][nf], &F[mf * 4], bb);
            }
    };

    #pragma unroll
    for (int s = 0; s < NST - 1; s++) { issue_stage(s); CP_COMMIT(); }

    uint32_t F[24];

    for (int kt = 0; kt < nk; kt++) {
        CP_WAIT();
        __syncthreads();
        const uint32_t base = sb + (uint32_t)(kt % NST) * STAGEB;
        if (kt + NST - 1 < nk) issue_stage(kt + NST - 1);
        CP_COMMIT();
        #pragma unroll
        for (int ks = 0; ks < 4; ks++) {
            load_frags(base, (uint32_t)ks * 32u, F);
            mma_step(F);
        }
    }

    // ---- epilogue ----
    const int g  = lane >> 2;
    const int tg = lane & 3;
    #pragma unroll
    for (int mf = 0; mf < 2; mf++) {
        const int r0 = bm + warpm * 32 + mf * 16 + g;
        #pragma unroll
        for (int nf = 0; nf < 8; nf++) {
            const int col = bn + warpn * 64 + nf * 8 + tg * 2;
            float v0 = acc[mf][nf][0], v1 = acc[mf][nf][1];
            float v2 = acc[mf][nf][2], v3 = acc[mf][nf][3];

            if (Cpart) {   // split-K fp32 partial, plane = blockIdx.z
                float* base2 = Cpart + (size_t)blockIdx.z * ((size_t)M * N);
                *(float2*)(base2 + (size_t)r0 * N + col)       = make_float2(v0, v1);
                *(float2*)(base2 + (size_t)(r0 + 8) * N + col) = make_float2(v2, v3);
                continue;
            }
            float b0 = bias[col], b1 = bias[col + 1];
            v0 += b0; v1 += b1; v2 += b0; v3 += b1;
            if (do_relu) {
                v0 = fmaxf(v0, 0.0f); v1 = fmaxf(v1, 0.0f);
                v2 = fmaxf(v2, 0.0f); v3 = fmaxf(v3, 0.0f);
            }
            if (Cf) {      // final: N==512; cols [0,256) mu, [256,512) logvar
                float* p0;
                float* p1;
                if (col < 256) {
                    p0 = Cf + (size_t)r0 * 256 + col;
                    p1 = Cf + (size_t)(r0 + 8) * 256 + col;
                } else {
                    float* half2p = Cf + (size_t)BATCH * 256;
                    p0 = half2p + (size_t)r0 * 256 + (col - 256);
                    p1 = half2p + (size_t)(r0 + 8) * 256 + (col - 256);
                }
                *(float2*)p0 = make_float2(v0, v1);
                *(float2*)p1 = make_float2(v2, v3);
            } else {
                *(uint32_t*)(Cs + (size_t)r0 * N + col)       = packh(v0, v1);
                *(uint32_t*)(Cs + (size_t)(r0 + 8) * N + col) = packh(v2, v3);
            }
        }
    }
}

// ---------------------------------------------------------------------------
// Launch: 10-node graph
// ---------------------------------------------------------------------------
extern "C" void kernel_launch(void* const* d_in, const int* in_sizes, int n_in,
                              void* d_out, int out_size)
{
    const float* x   = (const float*)d_in[0];
    const float* fw  = (const float*)d_in[1];
    const float* kp  = (const float*)d_in[2];
    const float* W1  = (const float*)d_in[3];
    const float* b1  = (const float*)d_in[4];
    const float* W2  = (const float*)d_in[5];
    const float* b2  = (const float*)d_in[6];
    const float* Wmu = (const float*)d_in[7];
    const float* bmu = (const float*)d_in[8];
    const float* Wlv = (const float*)d_in[9];
    const float* blv = (const float*)d_in[10];
    float* out = (float*)d_out;

    __half *Dt, *Dm, *W1f, *A1f, *W1ef, *x16, *h1_16, *h2_16, *W2f, *Wmlf;
    float *bml, *bscale, *part;
    cudaGetSymbolAddress((void**)&Dt,    g_Dt);
    cudaGetSymbolAddress((void**)&Dm,    g_Dm);
    cudaGetSymbolAddress((void**)&W1f,   g_W1f);
    cudaGetSymbolAddress((void**)&A1f,   g_A1f);
    cudaGetSymbolAddress((void**)&W1ef,  g_W1ef);
    cudaGetSymbolAddress((void**)&x16,   g_x16);
    cudaGetSymbolAddress((void**)&h1_16, g_h1_16);
    cudaGetSymbolAddress((void**)&h2_16, g_h2_16);
    cudaGetSymbolAddress((void**)&W2f,   g_W2f);
    cudaGetSymbolAddress((void**)&Wmlf,  g_Wmlf);
    cudaGetSymbolAddress((void**)&bml,   g_bml);
    cudaGetSymbolAddress((void**)&bscale, g_bscale);
    cudaGetSymbolAddress((void**)&part,  g_part);

    cudaFuncSetAttribute(gemm_f16,
                         cudaFuncAttributeMaxDynamicSharedMemorySize, SMEM_GEMM);

    // 1) setup: costab + bscale + bml (8192+2048+512 = 10752 threads)
    setup_kernel<<<42, 256>>>(fw, kp, bmu, blv);
    // 2) Dm + Dt via Chebyshev recurrences (32 elems/thread/matrix)
    build_D_kernel<<<(DIMN * 64) / 256, 256>>>();
    // 3) all fp32->fp16 converts in one kernel
    convert_all<<<(NTOT / 16 + 255) / 256, 256>>>(x, W1, W2, Wmu, Wlv);

    const int nW = 1024 * DIMN;

    // 4-5) A1[j][kf] = (sum_n W1[j][n] * Dm[kf][n]) * bscale[kf]  (split-K=2)
    gemm_f16<<<dim3(16, 8, 2), 256, SMEM_GEMM>>>(
        W1f, Dm, nullptr, nullptr, nullptr, part, 1024, 2048, 2048, 1024, 0);
    reduce2_f16<<<(nW / 4 + 255) / 256, 256>>>(part, bscale, A1f, nW, 2048);

    // 6-7) W1e[j][m] = sum_kf A1[j][kf] * Dt[m][kf]               (split-K=2)
    gemm_f16<<<dim3(16, 8, 2), 256, SMEM_GEMM>>>(
        A1f, Dt, nullptr, nullptr, nullptr, part, 1024, 2048, 2048, 1024, 0);
    reduce2_f16<<<(nW / 4 + 255) / 256, 256>>>(part, nullptr, W1ef, nW, 2048);

    // 8) h1 = relu(x @ W1e^T + b1)
    gemm_f16<<<dim3(8, 128, 1), 256, SMEM_GEMM>>>(
        x16, W1ef, b1, h1_16, nullptr, nullptr, BATCH, 1024, 2048, 2048, 1);
    // 9) h2 = relu(h1 @ W2^T + b2)
    gemm_f16<<<dim3(4, 128, 1), 256, SMEM_GEMM>>>(
        h1_16, W2f, b2, h2_16, nullptr, nullptr, BATCH, 512, 1024, 1024, 1);
    // 10) [mu | logvar] = h2 @ [Wmu;Wlv]^T + [bmu;blv]
    gemm_f16<<<dim3(4, 128, 1), 256, SMEM_GEMM>>>(
        h2_16, Wmlf, bml, nullptr, out, nullptr, BATCH, 512, 512, 512, 0);
}